// round 1
// baseline (speedup 1.0000x reference)
#include <cuda_runtime.h>

#define Bn 8
#define Hn 512
#define Wn 512
#define HW (Hn*Wn)
#define NPIX (Bn*HW)
#define NT4 (NPIX/4)

// Byte state layout: bits[0:4]=elem, bit4=fall_dir, bit5=grav, bit6=did_gravity
__device__ unsigned char g_A[NPIX];
__device__ unsigned char g_B[NPIX];

__constant__ unsigned char c_den[16]  = {1,4,3,2,0,4,4,0,4,3,3,2,3,4,0,0};
__constant__ unsigned char c_grv[16]  = {1,0,1,1,1,0,0,1,0,1,1,1,1,0,0,0};
__constant__ float         c_denf[16] = {1.f,4.f,3.f,2.f,0.f,4.f,4.f,0.f,4.f,3.f,3.f,2.f,3.f,4.f,0.f,0.f};

// ---------------------------------------------------------------------------
// Compress: world (B,20,H,W) f32 one-hot + rand -> byte grid (elem | fall<<4)
// ---------------------------------------------------------------------------
__global__ void __launch_bounds__(256) k_compress(
    const float* __restrict__ world, const float* __restrict__ rnd,
    unsigned char* __restrict__ out)
{
    int t = blockIdx.x * blockDim.x + threadIdx.x;
    if (t >= NT4) return;
    int pix = t * 4;
    int b   = pix >> 18;          // pix / HW
    int off = pix & (HW - 1);
    const float* wp = world + (size_t)b * 20 * HW + off;

    int e0 = 0, e1 = 0, e2 = 0, e3 = 0;
#pragma unroll
    for (int c = 1; c < 14; c++) {
        float4 v = *reinterpret_cast<const float4*>(wp + (size_t)c * HW);
        if (v.x > 0.5f) e0 = c;
        if (v.y > 0.5f) e1 = c;
        if (v.z > 0.5f) e2 = c;
        if (v.w > 0.5f) e3 = c;
    }
    float4 r = *reinterpret_cast<const float4*>(rnd + (size_t)b * HW + off);
    uchar4 s;
    s.x = (unsigned char)(e0 | ((r.x > 0.5f) << 4));
    s.y = (unsigned char)(e1 | ((r.y > 0.5f) << 4));
    s.z = (unsigned char)(e2 | ((r.z > 0.5f) << 4));
    s.w = (unsigned char)(e3 | ((r.w > 0.5f) << 4));
    *reinterpret_cast<uchar4*>(out + pix) = s;
}

// ---------------------------------------------------------------------------
// Gravity-bit pass: stone (elem 9) gets grav = (support<2) with support =
// stone[r-1,c-1]+stone[r-1,c+1], ZERO-padded at borders. Others: table grav.
// ---------------------------------------------------------------------------
__global__ void __launch_bounds__(256) k_gravbit(
    const unsigned char* __restrict__ in, unsigned char* __restrict__ out)
{
    int t = blockIdx.x * blockDim.x + threadIdx.x;
    if (t >= NT4) return;
    int pix = t * 4;
    int b   = pix >> 18;
    int off = pix & (HW - 1);
    int h   = off >> 9;
    int w4  = off & (Wn - 1);

    unsigned int S = *reinterpret_cast<const unsigned int*>(in + pix);

    unsigned int Am = 0, A0 = 0, Ap = 0;   // zero-pad default
    if (h > 0) {
        const unsigned char* ra = in + b * HW + (h - 1) * Wn;
        A0 = *reinterpret_cast<const unsigned int*>(ra + w4);
        if (w4 > 0)       Am = *reinterpret_cast<const unsigned int*>(ra + w4 - 4);
        if (w4 < Wn - 4)  Ap = *reinterpret_cast<const unsigned int*>(ra + w4 + 4);
    }
    // byte j of L = above-row byte (w4+j-1); byte j of R = above-row byte (w4+j+1)
    unsigned int L = (A0 << 8) | (Am >> 24);
    unsigned int R = (A0 >> 8) | (Ap << 24);

    unsigned int res = 0;
#pragma unroll
    for (int j = 0; j < 4; j++) {
        int s = (S >> (8 * j)) & 0xFF;
        int e = s & 15;
        int g;
        if (e == 9) {
            int sup = (((L >> (8 * j)) & 15) == 9) + (((R >> (8 * j)) & 15) == 9);
            g = (sup < 2);
        } else {
            g = c_grv[e];
        }
        res |= (unsigned int)(s | (g << 5)) << (8 * j);
    }
    *reinterpret_cast<unsigned int*>(out + pix) = res;
}

// ---------------------------------------------------------------------------
// Vertical gravity swap pass for density D (circular wrap in H).
// ---------------------------------------------------------------------------
template <int D>
__global__ void __launch_bounds__(256) k_grav(
    const unsigned char* __restrict__ in, unsigned char* __restrict__ out)
{
    int t = blockIdx.x * blockDim.x + threadIdx.x;
    if (t >= NT4) return;
    int pix = t * 4;
    int b   = pix >> 18;
    int off = pix & (HW - 1);
    int h   = off >> 9;
    int w4  = off & (Wn - 1);
    int base = b * HW;

    unsigned int S  = *reinterpret_cast<const unsigned int*>(in + pix);
    int ha = (h - 1) & (Hn - 1);
    int hb = (h + 1) & (Hn - 1);
    unsigned int SA = *reinterpret_cast<const unsigned int*>(in + base + ha * Wn + w4);
    unsigned int SB = *reinterpret_cast<const unsigned int*>(in + base + hb * Wn + w4);

    unsigned int res = 0;
#pragma unroll
    for (int j = 0; j < 4; j++) {
        int s  = (S  >> (8 * j)) & 0xFF;
        int a  = (SA >> (8 * j)) & 0xFF;
        int bb = (SB >> (8 * j)) & 0xFF;
        int ds = c_den[s & 15], da = c_den[a & 15], db = c_den[bb & 15];
        bool gs = s & 32, ga = a & 32, gb = bb & 32;

        bool becomes_below = (ds == D) && (ds > db) && gs && gb;   // take cell below
        bool becomes_above = (da == D) && (da > ds) && ga && gs;   // take cell above

        int src = becomes_below ? bb : (becomes_above ? a : s);
        int r = (src & 0x2F) | (s & 0x50) | (becomes_above ? 0x40 : 0);
        res |= (unsigned int)r << (8 * j);
    }
    *reinterpret_cast<unsigned int*>(out + pix) = res;
}

// ---------------------------------------------------------------------------
// Diagonal sand pass for element E, direction LEFT (circular wrap H and W).
// LEFT:  bl neighbor = (r+1,c-1), ar neighbor = (r-1,c+1), match = fall bit
// RIGHT: bl neighbor = (r+1,c+1), ar neighbor = (r-1,c-1), match = !fall bit
// ---------------------------------------------------------------------------
template <int E, bool LEFT>
__global__ void __launch_bounds__(256) k_diag(
    const unsigned char* __restrict__ in, unsigned char* __restrict__ out)
{
    int t = blockIdx.x * blockDim.x + threadIdx.x;
    if (t >= NT4) return;
    int pix = t * 4;
    int b   = pix >> 18;
    int off = pix & (HW - 1);
    int h   = off >> 9;
    int w4  = off & (Wn - 1);
    int base = b * HW;

    int ha = (h - 1) & (Hn - 1);
    int hb = (h + 1) & (Hn - 1);
    const unsigned char* ra = in + base + ha * Wn;
    const unsigned char* rb = in + base + hb * Wn;
    int wm = (w4 - 4) & (Wn - 1);
    int wp = (w4 + 4) & (Wn - 1);

    unsigned int S  = *reinterpret_cast<const unsigned int*>(in + pix);
    unsigned int B0 = *reinterpret_cast<const unsigned int*>(rb + w4);
    unsigned int A0 = *reinterpret_cast<const unsigned int*>(ra + w4);

    unsigned int BL, AR;
    if (LEFT) {
        unsigned int Bm = *reinterpret_cast<const unsigned int*>(rb + wm);
        unsigned int Ap = *reinterpret_cast<const unsigned int*>(ra + wp);
        BL = (B0 << 8) | (Bm >> 24);   // byte j = below-row byte (w+j-1)
        AR = (A0 >> 8) | (Ap << 24);   // byte j = above-row byte (w+j+1)
    } else {
        unsigned int Bp = *reinterpret_cast<const unsigned int*>(rb + wp);
        unsigned int Am = *reinterpret_cast<const unsigned int*>(ra + wm);
        BL = (B0 >> 8) | (Bp << 24);   // (w+j+1)
        AR = (A0 << 8) | (Am >> 24);   // (w+j-1)
    }

    unsigned int res = 0;
#pragma unroll
    for (int j = 0; j < 4; j++) {
        int s   = (S  >> (8 * j)) & 0xFF;
        int sbl = (BL >> (8 * j)) & 0xFF;
        int sar = (AR >> (8 * j)) & 0xFF;

        bool match_s  = LEFT ? (s   & 16) != 0 : (s   & 16) == 0;
        bool match_ar = LEFT ? (sar & 16) != 0 : (sar & 16) == 0;
        bool nds  = !(s & 64), ndbl = !(sbl & 64), ndar = !(sar & 64);
        int ds = c_den[s & 15], dbl = c_den[sbl & 15], dar = c_den[sar & 15];
        bool gs = s & 32, gbl = sbl & 32, gar = sar & 32;

        bool becomes_bl = ((s & 15) == E) && ndbl && nds && match_s  && (ds  > dbl) && gs  && gbl;
        bool becomes_ar = ((sar & 15) == E) && ndar && nds && match_ar && (dar > ds ) && gar && gs;

        int src = becomes_bl ? sbl : (becomes_ar ? sar : s);
        res |= (unsigned int)((src & 0x2F) | (s & 0x50)) << (8 * j);
    }
    *reinterpret_cast<unsigned int*>(out + pix) = res;
}

// ---------------------------------------------------------------------------
// Decompress: byte grid -> world (B,20,H,W) f32
// ---------------------------------------------------------------------------
__global__ void __launch_bounds__(256) k_decompress(
    const unsigned char* __restrict__ in, float* __restrict__ out)
{
    int t = blockIdx.x * blockDim.x + threadIdx.x;
    if (t >= NT4) return;
    int pix = t * 4;
    int b   = pix >> 18;
    int off = pix & (HW - 1);
    uchar4 s4 = *reinterpret_cast<const uchar4*>(in + pix);
    float* op = out + (size_t)b * 20 * HW + off;

    int e0 = s4.x & 15, e1 = s4.y & 15, e2 = s4.z & 15, e3 = s4.w & 15;
#pragma unroll
    for (int c = 0; c < 14; c++) {
        float4 v;
        v.x = (e0 == c) ? 1.f : 0.f;
        v.y = (e1 == c) ? 1.f : 0.f;
        v.z = (e2 == c) ? 1.f : 0.f;
        v.w = (e3 == c) ? 1.f : 0.f;
        *reinterpret_cast<float4*>(op + (size_t)c * HW) = v;
    }
    float4 d;
    d.x = c_denf[e0]; d.y = c_denf[e1]; d.z = c_denf[e2]; d.w = c_denf[e3];
    *reinterpret_cast<float4*>(op + (size_t)14 * HW) = d;
    float4 g;
    g.x = (float)((s4.x >> 5) & 1);
    g.y = (float)((s4.y >> 5) & 1);
    g.z = (float)((s4.z >> 5) & 1);
    g.w = (float)((s4.w >> 5) & 1);
    *reinterpret_cast<float4*>(op + (size_t)15 * HW) = g;
    float4 z = make_float4(0.f, 0.f, 0.f, 0.f);
#pragma unroll
    for (int c = 16; c < 20; c++)
        *reinterpret_cast<float4*>(op + (size_t)c * HW) = z;
}

// ---------------------------------------------------------------------------
extern "C" void kernel_launch(void* const* d_in, const int* in_sizes, int n_in,
                              void* d_out, int out_size)
{
    // world is the big input (8*20*512*512), rand is (8*1*512*512)
    int wi = 0, ri = 1;
    if (n_in >= 2 && in_sizes[0] < in_sizes[1]) { wi = 1; ri = 0; }
    const float* world = (const float*)d_in[wi];
    const float* rnd   = (const float*)d_in[ri];
    float* out = (float*)d_out;

    unsigned char *A, *B;
    cudaGetSymbolAddress((void**)&A, g_A);
    cudaGetSymbolAddress((void**)&B, g_B);

    const int threads = 256;
    const int blocks  = (NT4 + threads - 1) / threads;   // 2048

    k_compress<<<blocks, threads>>>(world, rnd, A);
    k_gravbit<<<blocks, threads>>>(A, B);
    k_grav<0><<<blocks, threads>>>(B, A);
    k_grav<1><<<blocks, threads>>>(A, B);
    k_grav<2><<<blocks, threads>>>(B, A);
    k_grav<3><<<blocks, threads>>>(A, B);
    k_diag<2,  true ><<<blocks, threads>>>(B, A);
    k_diag<2,  false><<<blocks, threads>>>(A, B);
    k_diag<12, true ><<<blocks, threads>>>(B, A);
    k_diag<12, false><<<blocks, threads>>>(A, B);
    k_decompress<<<blocks, threads>>>(B, out);
}

// round 2
// speedup vs baseline: 1.7104x; 1.7104x over previous
#include <cuda_runtime.h>

#define Bn 8
#define Hn 512
#define Wn 512
#define HW (Hn*Wn)
#define NPIX (Bn*HW)
#define NT4 (NPIX/4)

#define TR 16
#define HALO 7
#define RT (TR + 2*HALO)        // 30 tile rows
#define WW (Wn/2)               // 256 uints (2 px each) per row
#define TILE_WORDS (RT*WW)      // 7680
#define NTHREADS 512
#define NCHUNK (Hn/TR)          // 32
#define NBLK (Bn*NCHUNK)        // 256
#define SMEM_BYTES (2*TILE_WORDS*4)   // 61440

// 16-bit state: bits0-3 elem, bits4-6 density, bit7 grav, bit8 fall, bit9 did_gravity
__device__ unsigned short g_grid[NPIX];

// density LUT packed 3 bits/elem into a 64-bit immediate (no LDC at runtime)
__host__ __device__ constexpr unsigned long long make_den_lut() {
    constexpr int d[16] = {1,4,3,2,0,4,4,0,4,3,3,2,3,4,0,0};
    unsigned long long v = 0;
    for (int i = 0; i < 16; i++) v |= (unsigned long long)d[i] << (3*i);
    return v;
}
constexpr unsigned long long DEN_LUT = make_den_lut();
// gravity LUT: 1 bit/elem
#define GRV_LUT 0x1E9D

// ---------------------------------------------------------------------------
// Compress: world one-hot channels + rand -> 16-bit state grid.
// Also folds the stone-gravity rule (support = stone above-left + above-right,
// ZERO-padded at image borders in both H and W).
// ---------------------------------------------------------------------------
__global__ void __launch_bounds__(256) k_compress(
    const float* __restrict__ world, const float* __restrict__ rnd,
    unsigned short* __restrict__ grid)
{
    int t = blockIdx.x * blockDim.x + threadIdx.x;
    if (t >= NT4) return;
    int pix = t * 4;
    int b   = pix >> 18;
    int off = pix & (HW - 1);
    int h = off >> 9, w = off & (Wn - 1);
    const float* wp = world + (size_t)b * 20 * HW + off;

    int e0 = 0, e1 = 0, e2 = 0, e3 = 0;
#pragma unroll
    for (int c = 1; c < 14; c++) {
        float4 v = *reinterpret_cast<const float4*>(wp + (size_t)c * HW);
        if (v.x > 0.5f) e0 = c;
        if (v.y > 0.5f) e1 = c;
        if (v.z > 0.5f) e2 = c;
        if (v.w > 0.5f) e3 = c;
    }
    float4 r = *reinterpret_cast<const float4*>(rnd + (size_t)b * HW + off);

    // stone supports from the row above (zero-padded)
    float a0 = 0.f, a1 = 0.f, a2 = 0.f, a3 = 0.f, a4 = 0.f, a5 = 0.f;
    if (h > 0) {
        const float* p9 = world + (size_t)b * 20 * HW + (size_t)9 * HW + (size_t)(h - 1) * Wn;
        float4 m = *reinterpret_cast<const float4*>(p9 + w);
        a1 = m.x; a2 = m.y; a3 = m.z; a4 = m.w;
        if (w > 0)       a0 = p9[w - 1];
        if (w + 4 < Wn)  a5 = p9[w + 4];
    }

    int e[4]  = {e0, e1, e2, e3};
    float fr[4] = {r.x, r.y, r.z, r.w};
    float av[6] = {a0, a1, a2, a3, a4, a5};
    unsigned int s[4];
#pragma unroll
    for (int j = 0; j < 4; j++) {
        int ej  = e[j];
        int den = (int)((DEN_LUT >> (3 * ej)) & 7);
        int g;
        if (ej == 9) {
            int sup = (av[j] > 0.5f) + (av[j + 2] > 0.5f);
            g = (sup < 2);
        } else {
            g = (GRV_LUT >> ej) & 1;
        }
        s[j] = (unsigned int)(ej | (den << 4) | (g << 7) | ((fr[j] > 0.5f) << 8));
    }
    *reinterpret_cast<uint2*>(grid + pix) =
        make_uint2(s[0] | (s[1] << 16), s[2] | (s[3] << 16));
}

// ---------------------------------------------------------------------------
// Per-halfword step functions (operate on clean 16-bit values in 32-bit regs)
// ---------------------------------------------------------------------------
__device__ __forceinline__ unsigned int grav_half(
    unsigned int s, unsigned int a, unsigned int b, int D)
{
    int ds = (s >> 4) & 7, da = (a >> 4) & 7, db = (b >> 4) & 7;
    bool gs = s & 0x80, ga = a & 0x80, gb = b & 0x80;
    bool bel = (ds == D) && (db < D) && gs && gb;   // take cell below
    bool abv = (da == D) && (ds < D) && ga && gs;   // take cell above
    unsigned int src = bel ? b : (abv ? a : s);
    return (src & 0xFF) | (s & 0x300) | (abv ? 0x200u : 0u);
}

__device__ __forceinline__ unsigned int diag_half(
    unsigned int s, unsigned int bl, unsigned int ar, int E, int LEFT)
{
    bool ms  = (int)((s  >> 8) & 1) == LEFT;
    bool mar = (int)((ar >> 8) & 1) == LEFT;
    bool nds = !(s & 0x200), ndbl = !(bl & 0x200), ndar = !(ar & 0x200);
    int ds = (s >> 4) & 7, dbl = (bl >> 4) & 7, dar = (ar >> 4) & 7;
    bool gs = s & 0x80, gbl = bl & 0x80, gar = ar & 0x80;
    bool bbl = ((int)(s  & 15) == E) && ndbl && nds && ms  && (ds  > dbl) && gs  && gbl;
    bool bar = ((int)(ar & 15) == E) && ndar && nds && mar && (dar > ds ) && gar && gs;
    unsigned int src = bbl ? bl : (bar ? ar : s);
    return (src & 0xFF) | (s & 0x300);
}

// ---------------------------------------------------------------------------
// Fused sim (3 grav + 4 diag passes in SMEM) + decompress to f32 world.
// Block = one batch image x 16-row chunk, tile has 7-row halo each side.
// ---------------------------------------------------------------------------
extern __shared__ unsigned int smbuf[];

__global__ void __launch_bounds__(NTHREADS) k_sim(
    const unsigned short* __restrict__ grid, float* __restrict__ out)
{
    unsigned int* buf0 = smbuf;
    unsigned int* buf1 = smbuf + TILE_WORDS;
    int tid   = threadIdx.x;
    int b     = blockIdx.x / NCHUNK;
    int chunk = blockIdx.x % NCHUNK;
    int r0    = chunk * TR;
    const unsigned int* gsrc =
        reinterpret_cast<const unsigned int*>(grid + (size_t)b * HW);

    // Load tile (with vertical wrap) into buf0
    for (int idx = tid; idx < TILE_WORDS; idx += NTHREADS) {
        int i = idx >> 8, c = idx & 255;
        int gr = (r0 - HALO + i) & (Hn - 1);
        buf0[idx] = gsrc[gr * WW + c];
    }
    __syncthreads();

    unsigned int* sp = buf0;
    unsigned int* dp = buf1;

    // Gravity passes D = 1, 2, 3  (D=0 is provably a no-op)
#pragma unroll
    for (int D = 1; D <= 3; D++) {
        for (int idx = tid; idx < TILE_WORDS; idx += NTHREADS) {
            int i = idx >> 8, c = idx & 255;
            int im = i ? i - 1 : 0;              // edge rows are dead halo
            int ip = (i < RT - 1) ? i + 1 : RT - 1;
            unsigned int S = sp[idx];
            unsigned int A = sp[(im << 8) + c];
            unsigned int B = sp[(ip << 8) + c];
            unsigned int lo = grav_half(S & 0xFFFF, A & 0xFFFF, B & 0xFFFF, D);
            unsigned int hi = grav_half(S >> 16,    A >> 16,    B >> 16,    D);
            dp[idx] = lo | (hi << 16);
        }
        __syncthreads();
        unsigned int* t = sp; sp = dp; dp = t;
    }

    // Diagonal passes: (E, LEFT) = (2,1), (2,0), (12,1), (12,0)
#pragma unroll
    for (int p = 0; p < 4; p++) {
        const int E    = (p < 2) ? 2 : 12;
        const int LEFT = !(p & 1);
        for (int idx = tid; idx < TILE_WORDS; idx += NTHREADS) {
            int i = idx >> 8, c = idx & 255;
            int im = i ? i - 1 : 0;
            int ip = (i < RT - 1) ? i + 1 : RT - 1;
            int cm = (c - 1) & 255, cp = (c + 1) & 255;   // horizontal wrap
            unsigned int S  = sp[idx];
            unsigned int A0 = sp[(im << 8) + c];
            unsigned int B0 = sp[(ip << 8) + c];
            unsigned int BL, AR;
            if (LEFT) {
                unsigned int Bm = sp[(ip << 8) + cm];
                unsigned int Ap = sp[(im << 8) + cp];
                BL = (Bm >> 16) | (B0 << 16);   // below, col-1
                AR = (A0 >> 16) | (Ap << 16);   // above, col+1
            } else {
                unsigned int Bp = sp[(ip << 8) + cp];
                unsigned int Am = sp[(im << 8) + cm];
                BL = (B0 >> 16) | (Bp << 16);   // below, col+1
                AR = (Am >> 16) | (A0 << 16);   // above, col-1
            }
            unsigned int lo = diag_half(S & 0xFFFF, BL & 0xFFFF, AR & 0xFFFF, E, LEFT);
            unsigned int hi = diag_half(S >> 16,    BL >> 16,    AR >> 16,    E, LEFT);
            dp[idx] = lo | (hi << 16);
        }
        __syncthreads();
        unsigned int* t = sp; sp = dp; dp = t;
    }

    // Decompress valid rows [HALO, HALO+TR) to the 20-channel f32 world
    float* ob = out + (size_t)b * 20 * HW;
    for (int g = tid; g < TR * (Wn / 4); g += NTHREADS) {
        int i  = (g >> 7) + HALO;
        int wq = (g & 127) << 2;
        unsigned int u0 = sp[(i << 8) + (wq >> 1)];
        unsigned int u1 = sp[(i << 8) + (wq >> 1) + 1];
        int s0 = u0 & 0xFFFF, s1 = u0 >> 16, s2 = u1 & 0xFFFF, s3 = u1 >> 16;
        int gh = r0 + i - HALO;
        float* op = ob + (size_t)gh * Wn + wq;
        int e0 = s0 & 15, e1 = s1 & 15, e2 = s2 & 15, e3 = s3 & 15;
#pragma unroll
        for (int c = 0; c < 14; c++) {
            float4 v = make_float4(e0 == c ? 1.f : 0.f, e1 == c ? 1.f : 0.f,
                                   e2 == c ? 1.f : 0.f, e3 == c ? 1.f : 0.f);
            *reinterpret_cast<float4*>(op + (size_t)c * HW) = v;
        }
        *reinterpret_cast<float4*>(op + (size_t)14 * HW) =
            make_float4((float)((s0 >> 4) & 7), (float)((s1 >> 4) & 7),
                        (float)((s2 >> 4) & 7), (float)((s3 >> 4) & 7));
        *reinterpret_cast<float4*>(op + (size_t)15 * HW) =
            make_float4((float)((s0 >> 7) & 1), (float)((s1 >> 7) & 1),
                        (float)((s2 >> 7) & 1), (float)((s3 >> 7) & 1));
        float4 z = make_float4(0.f, 0.f, 0.f, 0.f);
#pragma unroll
        for (int c = 16; c < 20; c++)
            *reinterpret_cast<float4*>(op + (size_t)c * HW) = z;
    }
}

// ---------------------------------------------------------------------------
extern "C" void kernel_launch(void* const* d_in, const int* in_sizes, int n_in,
                              void* d_out, int out_size)
{
    int wi = 0, ri = 1;
    if (n_in >= 2 && in_sizes[0] < in_sizes[1]) { wi = 1; ri = 0; }
    const float* world = (const float*)d_in[wi];
    const float* rnd   = (const float*)d_in[ri];
    float* out = (float*)d_out;

    unsigned short* grid;
    cudaGetSymbolAddress((void**)&grid, g_grid);

    cudaFuncSetAttribute(k_sim, cudaFuncAttributeMaxDynamicSharedMemorySize,
                         SMEM_BYTES);

    k_compress<<<NT4 / 256, 256>>>(world, rnd, grid);
    k_sim<<<NBLK, NTHREADS, SMEM_BYTES>>>(grid, out);
}

// round 5
// speedup vs baseline: 3.3156x; 1.9385x over previous
#include <cuda_runtime.h>

#define Bn 8
#define Hn 512
#define Wn 512
#define HW (Hn*Wn)
#define NPIX (Bn*HW)
#define WPR 16                 // 32-px words per row
#define PW (NPIX/32)           // words per bit-plane = 65536
#define TR 16
#define HALO 7
#define RT (TR+2*HALO)         // 30 tile rows
#define ITEMS (RT*WPR)         // 480
#define NTH 512
#define NBLK (Bn*(Hn/TR))      // 256

// Bit-plane grid: planes 0-3 elem bits, 4-6 density bits, 7 grav, 8 fall
__device__ unsigned int g_bp[9 * PW];

__host__ __device__ constexpr unsigned long long make_den_lut() {
    constexpr int d[16] = {1,4,3,2,0,4,4,0,4,3,3,2,3,4,0,0};
    unsigned long long v = 0;
    for (int i = 0; i < 16; i++) v |= (unsigned long long)d[i] << (3*i);
    return v;
}
constexpr unsigned long long DEN_LUT = make_den_lut();
#define GRV_LUT 0x1E9D

// ---------------------------------------------------------------------------
// Compress: one-hot world + rand -> 9 bit-planes (ballot-packed).
// Folds the stone gravity rule (supports zero-padded at image borders).
// ---------------------------------------------------------------------------
__global__ void __launch_bounds__(256) k_compress(
    const float* __restrict__ world, const float* __restrict__ rnd,
    unsigned int* __restrict__ bp)
{
    int t = blockIdx.x * 256 + threadIdx.x;      // one thread = one pixel
    int b = t >> 18;
    int off = t & (HW - 1);
    int h = off >> 9, w = off & 511;
    const float* wpix = world + (size_t)b * 20 * HW + off;

    int e = 0;
#pragma unroll
    for (int c = 1; c < 14; c++)
        if (wpix[(size_t)c * HW] > 0.5f) e = c;
    float r = rnd[(size_t)b * HW + off];
    int den = (int)((DEN_LUT >> (3 * e)) & 7);
    int g;
    if (e == 9) {
        float sl = 0.f, sr = 0.f;
        if (h > 0) {
            const float* p9 = world + (size_t)b * 20 * HW + (size_t)9 * HW
                            + (size_t)(h - 1) * Wn;
            if (w > 0)   sl = p9[w - 1];
            if (w < 511) sr = p9[w + 1];
        }
        g = ((sl > 0.5f) + (sr > 0.5f)) < 2;
    } else {
        g = (GRV_LUT >> e) & 1;
    }

    unsigned m0 = __ballot_sync(~0u, e & 1);
    unsigned m1 = __ballot_sync(~0u, e & 2);
    unsigned m2 = __ballot_sync(~0u, e & 4);
    unsigned m3 = __ballot_sync(~0u, e & 8);
    unsigned m4 = __ballot_sync(~0u, den & 1);
    unsigned m5 = __ballot_sync(~0u, den & 2);
    unsigned m6 = __ballot_sync(~0u, den & 4);
    unsigned m7 = __ballot_sync(~0u, g);
    unsigned m8 = __ballot_sync(~0u, r > 0.5f);

    int lane = threadIdx.x & 31;
    unsigned widx = (unsigned)t >> 5;            // uniform across warp
    unsigned v = m0;
    v = lane == 1 ? m1 : v;  v = lane == 2 ? m2 : v;
    v = lane == 3 ? m3 : v;  v = lane == 4 ? m4 : v;
    v = lane == 5 ? m5 : v;  v = lane == 6 ? m6 : v;
    v = lane == 7 ? m7 : v;  v = lane == 8 ? m8 : v;
    if (lane < 9) bp[lane * PW + widx] = v;
}

// ---------------------------------------------------------------------------
// Bitwise helpers (32 pixels per op)
// ---------------------------------------------------------------------------
__device__ __forceinline__ unsigned eq_den(const unsigned* p, int D) {
    unsigned b0 = (D & 1) ? p[4] : ~p[4];
    unsigned b1 = (D & 2) ? p[5] : ~p[5];
    unsigned b2 = (D & 4) ? p[6] : ~p[6];
    return b0 & b1 & b2;
}
__device__ __forceinline__ unsigned lt_den(const unsigned* p, int D) {
    if (D == 1) return ~p[6] & ~p[5] & ~p[4];
    if (D == 2) return ~p[6] & ~p[5];
    return ~p[6] & ~(p[5] & p[4]);              // D == 3
}
__device__ __forceinline__ unsigned eq_elem(const unsigned* p, int E) {
    unsigned b0 = (E & 1) ? p[0] : ~p[0];
    unsigned b1 = (E & 2) ? p[1] : ~p[1];
    unsigned b2 = (E & 4) ? p[2] : ~p[2];
    unsigned b3 = (E & 8) ? p[3] : ~p[3];
    return b0 & b1 & b2 & b3;
}
// 3-bit unsigned compare x > y, bit-sliced
__device__ __forceinline__ unsigned gt3(
    unsigned x2, unsigned x1, unsigned x0,
    unsigned y2, unsigned y1, unsigned y0)
{
    unsigned eq2 = ~(x2 ^ y2), eq1 = ~(x1 ^ y1);
    return (x2 & ~y2) | (eq2 & x1 & ~y1) | (eq2 & eq1 & x0 & ~y0);
}

__shared__ unsigned s_mov[2][8][ITEMS];
__shared__ unsigned s_fall[ITEMS];
__shared__ unsigned s_dg[ITEMS];

template <int D>
__device__ __forceinline__ void grav_pass(
    unsigned (*src)[ITEMS], unsigned (*dst)[ITEMS], int rw)
{
    int i = rw >> 4, wq = rw & 15;
    int ia = i ? i - 1 : 0;
    int ib = (i < RT - 1) ? i + 1 : RT - 1;
    int ra = ia * WPR + wq, rb = ib * WPR + wq;
    unsigned s[8], a[8], bb[8];
#pragma unroll
    for (int p = 0; p < 8; p++) { s[p] = src[p][rw]; a[p] = src[p][ra]; bb[p] = src[p][rb]; }
    unsigned bel = eq_den(s, D) & lt_den(bb, D) & s[7] & bb[7];
    unsigned abv = eq_den(a, D) & lt_den(s, D) & a[7] & s[7];
    unsigned keep = ~(bel | abv);
#pragma unroll
    for (int p = 0; p < 8; p++)
        dst[p][rw] = (bel & bb[p]) | (abv & a[p]) | (keep & s[p]);
    s_dg[rw] |= abv;                 // own-slot RMW only: race-free
}

template <int E, int LEFT>
__device__ __forceinline__ void diag_pass(
    unsigned (*src)[ITEMS], unsigned (*dst)[ITEMS], int rw)
{
    int i = rw >> 4, wq = rw & 15;
    int ia = i ? i - 1 : 0;
    int ib = (i < RT - 1) ? i + 1 : RT - 1;
    int wm = (wq - 1) & 15, wp = (wq + 1) & 15;
    int ba = ia * WPR, bbr = ib * WPR;

    unsigned s[8], bl[8], ar[8];
#pragma unroll
    for (int p = 0; p < 8; p++) s[p] = src[p][rw];
    unsigned sd = s_dg[rw], sf = s_fall[rw];
    unsigned bl_dg, ar_dg, ar_f;
    if (LEFT) {
#pragma unroll
        for (int p = 0; p < 8; p++) {
            bl[p] = __funnelshift_l(src[p][bbr + wm], src[p][bbr + wq], 1); // below, c-1
            ar[p] = __funnelshift_r(src[p][ba + wq], src[p][ba + wp], 1);   // above, c+1
        }
        bl_dg = __funnelshift_l(s_dg[bbr + wm], s_dg[bbr + wq], 1);
        ar_dg = __funnelshift_r(s_dg[ba + wq], s_dg[ba + wp], 1);
        ar_f  = __funnelshift_r(s_fall[ba + wq], s_fall[ba + wp], 1);
    } else {
#pragma unroll
        for (int p = 0; p < 8; p++) {
            bl[p] = __funnelshift_r(src[p][bbr + wq], src[p][bbr + wp], 1); // below, c+1
            ar[p] = __funnelshift_l(src[p][ba + wm], src[p][ba + wq], 1);   // above, c-1
        }
        bl_dg = __funnelshift_r(s_dg[bbr + wq], s_dg[bbr + wp], 1);
        ar_dg = __funnelshift_l(s_dg[ba + wm], s_dg[ba + wq], 1);
        ar_f  = __funnelshift_l(s_fall[ba + wm], s_fall[ba + wq], 1);
    }
    unsigned ms  = LEFT ? sf : ~sf;
    unsigned mar = LEFT ? ar_f : ~ar_f;
    unsigned bbl = eq_elem(s, E) & ~bl_dg & ~sd & ms
                 & gt3(s[6], s[5], s[4], bl[6], bl[5], bl[4]) & s[7] & bl[7];
    unsigned bar = eq_elem(ar, E) & ~ar_dg & ~sd & mar
                 & gt3(ar[6], ar[5], ar[4], s[6], s[5], s[4]) & ar[7] & s[7];
    unsigned keep = ~(bbl | bar);
#pragma unroll
    for (int p = 0; p < 8; p++)
        dst[p][rw] = (bbl & bl[p]) | (bar & ar[p]) | (keep & s[p]);
}

// ---------------------------------------------------------------------------
// Fused sim (bit-sliced, 7 passes) + decompress to f32 world
// ---------------------------------------------------------------------------
__global__ void __launch_bounds__(NTH, 2) k_sim(
    const unsigned int* __restrict__ bp, float* __restrict__ out)
{
    int tid = threadIdx.x;
    int b = blockIdx.x >> 5, chunk = blockIdx.x & 31;
    int r0 = chunk * TR;

    // Load 9 planes (with vertical wrap) into SMEM
#pragma unroll
    for (int p = 0; p < 9; p++) {
        const unsigned* pp = bp + (size_t)p * PW + (size_t)b * (Hn * WPR);
        for (int rw = tid; rw < ITEMS; rw += NTH) {
            int i = rw >> 4, wq = rw & 15;
            int gr = (r0 - HALO + i) & (Hn - 1);
            unsigned v = pp[gr * WPR + wq];
            if (p < 8) s_mov[0][p][rw] = v; else s_fall[rw] = v;
        }
    }
    for (int rw = tid; rw < ITEMS; rw += NTH) s_dg[rw] = 0;
    __syncthreads();

    bool act = tid < ITEMS;
    if (act) grav_pass<1>(s_mov[0], s_mov[1], tid);        __syncthreads();
    if (act) grav_pass<2>(s_mov[1], s_mov[0], tid);        __syncthreads();
    if (act) grav_pass<3>(s_mov[0], s_mov[1], tid);        __syncthreads();
    if (act) diag_pass<2, 1>(s_mov[1], s_mov[0], tid);     __syncthreads();
    if (act) diag_pass<2, 0>(s_mov[0], s_mov[1], tid);     __syncthreads();
    if (act) diag_pass<12, 1>(s_mov[1], s_mov[0], tid);    __syncthreads();
    if (act) diag_pass<12, 0>(s_mov[0], s_mov[1], tid);    __syncthreads();
    // final state in s_mov[1]

    // Decompress valid rows to the 20-channel f32 world
    float* ob = out + (size_t)b * 20 * HW;
    for (int g2 = tid; g2 < TR * 128; g2 += NTH) {
        int i  = (g2 >> 7) + HALO;
        int q  = g2 & 127;                 // float4 group within row
        int wq = q >> 3;
        int k  = (q & 7) * 4;
        int rw = i * WPR + wq;
        unsigned p0 = s_mov[1][0][rw], p1 = s_mov[1][1][rw];
        unsigned p2 = s_mov[1][2][rw], p3 = s_mov[1][3][rw];
        unsigned p4 = s_mov[1][4][rw], p5 = s_mov[1][5][rw];
        unsigned p6 = s_mov[1][6][rw], p7 = s_mov[1][7][rw];
        int e[4]; float dn[4], gv[4];
#pragma unroll
        for (int j = 0; j < 4; j++) {
            int kk = k + j;
            e[j] = ((p0 >> kk) & 1) | (((p1 >> kk) & 1) << 1)
                 | (((p2 >> kk) & 1) << 2) | (((p3 >> kk) & 1) << 3);
            dn[j] = (float)(((p4 >> kk) & 1) | (((p5 >> kk) & 1) << 1)
                          | (((p6 >> kk) & 1) << 2));
            gv[j] = (float)((p7 >> kk) & 1);
        }
        int gh = r0 + i - HALO;
        float* op = ob + (size_t)gh * Wn + q * 4;
#pragma unroll
        for (int c = 0; c < 14; c++) {
            float4 v = make_float4(e[0] == c ? 1.f : 0.f, e[1] == c ? 1.f : 0.f,
                                   e[2] == c ? 1.f : 0.f, e[3] == c ? 1.f : 0.f);
            *reinterpret_cast<float4*>(op + (size_t)c * HW) = v;
        }
        *reinterpret_cast<float4*>(op + (size_t)14 * HW) =
            make_float4(dn[0], dn[1], dn[2], dn[3]);
        *reinterpret_cast<float4*>(op + (size_t)15 * HW) =
            make_float4(gv[0], gv[1], gv[2], gv[3]);
        float4 z = make_float4(0.f, 0.f, 0.f, 0.f);
#pragma unroll
        for (int c = 16; c < 20; c++)
            *reinterpret_cast<float4*>(op + (size_t)c * HW) = z;
    }
}

// ---------------------------------------------------------------------------
extern "C" void kernel_launch(void* const* d_in, const int* in_sizes, int n_in,
                              void* d_out, int out_size)
{
    int wi = 0, ri = 1;
    if (n_in >= 2 && in_sizes[0] < in_sizes[1]) { wi = 1; ri = 0; }
    const float* world = (const float*)d_in[wi];
    const float* rnd   = (const float*)d_in[ri];
    float* out = (float*)d_out;

    unsigned int* bp;
    cudaGetSymbolAddress((void**)&bp, g_bp);

    k_compress<<<NPIX / 256, 256>>>(world, rnd, bp);
    k_sim<<<NBLK, NTH>>>(bp, out);
}